// round 17
// baseline (speedup 1.0000x reference)
#include <cuda_runtime.h>
#include <math.h>

#define HW 128
#define NPIX (HW*HW)
#define NF 512
#define NP 256
#define SIGMAINV 7000.0f
#define BBOX_M 0.06f
#define DLB_T 0.055f

__device__ __forceinline__ float seg_d2(float px, float py, float ax, float ay,
                                        float bx, float by) {
    float abx = bx - ax, aby = by - ay;
    float apx = px - ax, apy = py - ay;
    float t = __fdividef(apx * abx + apy * aby, abx * abx + aby * aby + 1e-10f);
    t = fminf(fmaxf(t, 0.0f), 1.0f);
    float dx = apx - t * abx;
    float dy = apy - t * aby;
    return dx * dx + dy * dy;
}

// Single fused kernel. Block = 512 threads = 16 warps = one 8x4-pixel patch
// (lane = pixel; faces split 16 ways across warps).
// blockIdx is permuted -> patch so heavy screen regions scatter across SMs.
// Phase 0: block-local preprocessing into SMEM (1 vertex / 1 face per thread).
// Phase 1: deterministic compaction of bbox survivors into s_list.
// Phase 2: warps take list entries round-robin (j = wid, += 16).
// Phase 3: smem reduction over 16 warps; warp 0 gathers winner colors + writes.
__global__ __launch_bounds__(512)
void raster_fused(float* __restrict__ out,
                  const float* __restrict__ pts,
                  const float* __restrict__ cols,
                  const float* __restrict__ rot,
                  const float* __restrict__ cpos,
                  const float* __restrict__ proj,
                  const int* __restrict__ faces) {
    __shared__ float s_vx[NP], s_vy[NP], s_cx[NP], s_cy[NP], s_cz[NP];
    __shared__ float4 s_A[NF];   // x0,y0,x1,y1
    __shared__ float4 s_B[NF];   // x2,y2,invden,h0
    __shared__ float4 s_C[NF];   // h1,h2,z0,z1
    __shared__ float s_z2[NF];
    __shared__ unsigned s_words[16];
    __shared__ int s_cnt;
    __shared__ short s_list[NF];
    __shared__ float s_rz[16][32], s_rw0[16][32], s_rw1[16][32], s_rw2[16][32], s_rp[16][32];
    __shared__ int s_rf[16][32];

    int t = threadIdx.x;
    int lane = t & 31;
    int wid = t >> 5;                 // 0..15
    int b = (blockIdx.x * 331) & 511; // odd multiplier -> bijection on [0,512)
    int px0 = (b & 15) * 8;           // 16 patches across
    int py0 = (b >> 4) * 4;           // 32 patch-rows
    int ix = px0 + (lane & 7);
    int iy = py0 + (lane >> 3);

    float px = (ix + 0.5f) * (2.0f / HW) - 1.0f;
    float py = 1.0f - (iy + 0.5f) * (2.0f / HW);

    // patch NDC bounds (pixel centers)
    float xmn = (px0 + 0.5f) * (2.0f / HW) - 1.0f;
    float xmx = (px0 + 7.5f) * (2.0f / HW) - 1.0f;
    float ymx = 1.0f - (py0 + 0.5f) * (2.0f / HW);
    float ymn = 1.0f - (py0 + 3.5f) * (2.0f / HW);

    // ---- Phase 0a: per-vertex transform (threads 0..255) ----
    if (t < NP) {
        float r00 = rot[0], r01 = rot[1], r02 = rot[2];
        float r10 = rot[3], r11 = rot[4], r12 = rot[5];
        float r20 = rot[6], r21 = rot[7], r22 = rot[8];
        float cx = cpos[0], cy = cpos[1], cz = cpos[2];
        float pr0 = proj[0], pr1 = proj[1], pr2 = proj[2];

        float qx = pts[t * 3 + 0] - cx;
        float qy = pts[t * 3 + 1] - cy;
        float qz = pts[t * 3 + 2] - cz;
        float X = qx * r00 + qy * r01 + qz * r02;
        float Y = qx * r10 + qy * r11 + qz * r12;
        float Z = qx * r20 + qy * r21 + qz * r22;
        s_cx[t] = X; s_cy[t] = Y; s_cz[t] = Z;
        s_vx[t] = (X * pr0) / (Z * pr2);
        s_vy[t] = (Y * pr1) / (Z * pr2);
    }
    __syncthreads();

    // ---- Phase 0b: per-face tables (1 face / thread) + bbox ballot ----
    {
        int f = t;
        int i0 = faces[f * 3 + 0];
        int i1 = faces[f * 3 + 1];
        int i2 = faces[f * 3 + 2];
        float x0 = s_vx[i0], y0 = s_vy[i0];
        float x1 = s_vx[i1], y1 = s_vy[i1];
        float x2 = s_vx[i2], y2 = s_vy[i2];

        // normal z in camera space (only x,y components of edges needed)
        float e1x = s_cx[i1] - s_cx[i0], e1y = s_cy[i1] - s_cy[i0];
        float e2x = s_cx[i2] - s_cx[i0], e2y = s_cy[i2] - s_cy[i0];
        float nz = e1x * e2y - e1y * e2x;

        float area = (x1 - x0) * (y2 - y0) - (x2 - x0) * (y1 - y0);
        bool ok = (nz > 0.0f) && (fabsf(area) > 1e-10f);

        // margin bbox test (poisoned by ok)
        float bxm = fminf(fminf(x0, x1), x2) - BBOX_M;
        float bxM = fmaxf(fmaxf(x0, x1), x2) + BBOX_M;
        float bym = fminf(fminf(y0, y1), y2) - BBOX_M;
        float byM = fmaxf(fmaxf(y0, y1), y2) + BBOX_M;
        bool ov = ok && (bxm <= xmx) && (bxM >= xmn) && (bym <= ymx) && (byM >= ymn);
        unsigned bal = __ballot_sync(0xFFFFFFFFu, ov);
        if (lane == 0) s_words[wid] = bal;

        float aabs = fabsf(area);
        float L0s = (x2 - x1) * (x2 - x1) + (y2 - y1) * (y2 - y1);
        float L1s = (x0 - x2) * (x0 - x2) + (y0 - y2) * (y0 - y2);
        float L2s = (x1 - x0) * (x1 - x0) + (y1 - y0) * (y1 - y0);
        float h0 = aabs * rsqrtf(fmaxf(L0s, 1e-40f));
        float h1 = aabs * rsqrtf(fmaxf(L1s, 1e-40f));
        float h2 = aabs * rsqrtf(fmaxf(L2s, 1e-40f));

        s_A[f] = make_float4(x0, y0, x1, y1);
        s_B[f] = make_float4(x2, y2, ok ? (1.0f / area) : 0.0f, h0);
        s_C[f] = make_float4(h1, h2, s_cz[i0], s_cz[i1]);
        s_z2[f] = s_cz[i2];

        // block 0 additionally writes the normalized normals output
        if (blockIdx.x == 0) {
            float e1z = s_cz[i1] - s_cz[i0];
            float e2z = s_cz[i2] - s_cz[i0];
            float nxx = e1y * e2z - e1z * e2y;
            float nyy = e1z * e2x - e1x * e2z;
            float nlen = sqrtf(nxx * nxx + nyy * nyy + nz * nz + 1e-8f);
            float ninv = 1.0f / (nlen + 1e-15f);
            out[NPIX * 4 + f * 3 + 0] = nxx * ninv;
            out[NPIX * 4 + f * 3 + 1] = nyy * ninv;
            out[NPIX * 4 + f * 3 + 2] = nz * ninv;
        }
    }
    __syncthreads();

    // ---- Phase 1: deterministic compaction by warp 0 ----
    if (wid == 0) {
        unsigned wv = (lane < 16) ? s_words[lane] : 0u;
        int c = __popc(wv);
        int s = c;
#pragma unroll
        for (int off = 1; off < 32; off <<= 1) {
            int n = __shfl_up_sync(0xFFFFFFFFu, s, off);
            if (lane >= off) s += n;
        }
        if (lane == 15) s_cnt = s;
        if (lane < 16) {
            int pos = s - c;
            int base = lane * 32;
            unsigned m = wv;
            while (m) {
                int bit = __ffs(m) - 1;
                m &= m - 1;
                s_list[pos++] = (short)(base + bit);
            }
        }
    }
    __syncthreads();

    int cnt = s_cnt;
    float prodv = 1.0f;
    float zb = 3.0e38f;
    float w0b = 0.0f, w1b = 0.0f, w2b = 0.0f;
    int fb = 0x7FFFFFFF;

    // ---- Phase 2: balanced, predicated face loop (16-way split) ----
    for (int j = wid; j < cnt; j += 16) {
        int f = s_list[j];
        float4 A = s_A[f];
        float4 B = s_B[f];
        float4 C = s_C[f];
        float z2v = s_z2[f];

        float w0 = ((A.z - px) * (B.y - py) - (B.x - px) * (A.w - py)) * B.z;
        float w1 = ((B.x - px) * (A.y - py) - (A.x - px) * (B.y - py)) * B.z;
        float w2 = 1.0f - w0 - w1;

        bool inside = (w0 >= 0.0f) && (w1 >= 0.0f) && (w2 >= 0.0f);
        float z = w0 * C.z + w1 * C.w + w2 * z2v;
        // argmin-first semantics: smaller z, ties -> smaller face index
        bool better = inside && (z < zb || (z == zb && f < fb));
        zb  = better ? z  : zb;
        fb  = better ? f  : fb;
        w0b = better ? w0 : w0b;
        w1b = better ? w1 : w1b;
        w2b = better ? w2 : w2b;
        prodv = inside ? 0.0f : prodv;   // probf = 1 inside

        // lower bound on distance; if >= DLB_T, (1-probf)==1.0f exactly
        float dlb = fmaxf(fmaxf(-w0 * B.w, -w1 * C.x), -w2 * C.y);
        bool need = (!inside) && (prodv != 0.0f) && (dlb < DLB_T);
        if (__any_sync(0xFFFFFFFFu, need)) {
            float d2 = seg_d2(px, py, A.x, A.y, A.z, A.w);
            d2 = fminf(d2, seg_d2(px, py, A.z, A.w, B.x, B.y));
            d2 = fminf(d2, seg_d2(px, py, B.x, B.y, A.x, A.y));
            float e = __expf(-d2 * SIGMAINV);
            prodv = need ? prodv * (1.0f - e) : prodv;
        }
    }

    // ---- Phase 3: combine the 16 per-warp partials (lane = pixel) ----
    s_rz[wid][lane] = zb;
    s_rf[wid][lane] = fb;
    s_rw0[wid][lane] = w0b;
    s_rw1[wid][lane] = w1b;
    s_rw2[wid][lane] = w2b;
    s_rp[wid][lane] = prodv;
    __syncthreads();

    if (wid == 0) {
#pragma unroll
        for (int k = 1; k < 16; k++) {
            float oz = s_rz[k][lane];
            int of = s_rf[k][lane];
            prodv *= s_rp[k][lane];
            if (oz < zb || (oz == zb && of < fb)) {
                zb = oz; fb = of;
                w0b = s_rw0[k][lane];
                w1b = s_rw1[k][lane];
                w2b = s_rw2[k][lane];
            }
        }

        float rr = 0.0f, gg = 0.0f, bc = 0.0f;
        if (fb != 0x7FFFFFFF) {
            int i0 = faces[fb * 3 + 0];
            int i1 = faces[fb * 3 + 1];
            int i2 = faces[fb * 3 + 2];
            rr = w0b * cols[i0 * 3 + 0] + w1b * cols[i1 * 3 + 0] + w2b * cols[i2 * 3 + 0];
            gg = w0b * cols[i0 * 3 + 1] + w1b * cols[i1 * 3 + 1] + w2b * cols[i2 * 3 + 1];
            bc = w0b * cols[i0 * 3 + 2] + w1b * cols[i1 * 3 + 2] + w2b * cols[i2 * 3 + 2];
        }

        int p = iy * HW + ix;
        out[p * 3 + 0] = rr;
        out[p * 3 + 1] = gg;
        out[p * 3 + 2] = bc;
        out[NPIX * 3 + p] = 1.0f - prodv;
    }
}

extern "C" void kernel_launch(void* const* d_in, const int* in_sizes, int n_in,
                              void* d_out, int out_size) {
    const float* pts  = (const float*)d_in[0];
    const float* cols = (const float*)d_in[1];
    const float* rot  = (const float*)d_in[2];
    const float* cpos = (const float*)d_in[3];
    const float* proj = (const float*)d_in[4];
    const int*   fcs  = (const int*)d_in[5];
    float* out = (float*)d_out;

    raster_fused<<<NPIX / 32, 512>>>(out, pts, cols, rot, cpos, proj, fcs);
}